// round 7
// baseline (speedup 1.0000x reference)
#include <cuda_runtime.h>
#include <cuda_fp16.h>
#include <cuda_pipeline.h>

// S=64, B=128, D=10000 fixed by the reference.
#define D_DIM   10000
#define D4      2500
#define J_FULL  78            // 78*32 = 2496 float4; tail = 4 (lane<4)
#define S_DIM   64
#define B_DIM   128
#define THREADS 1024
#define NWARPS  32
#define DEPTH   4

#define RING_BYTES (DEPTH * THREADS * 16)        // 65536
#define TY_BYTES   (D_DIM * 4)                   // 40000 (half2 per element)
#define SMEM_BYTES (RING_BYTES + TY_BYTES)       // 105536

#define L2E 1.4426950408889634f

__device__ float    g_partial[B_DIM];
__device__ unsigned g_ticket;      // zero-init; reset by last CTA each launch

__device__ __forceinline__ float ex2f(float x) {
    float r;
    asm("ex2.approx.ftz.f32 %0, %1;" : "=f"(r) : "f"(x));
    return r;
}

union TyPack { __half2 h[4]; float4 f; };

// consume one quad: n = noise float4, typ = 4x half2 (theta*log2e, y)
__device__ __forceinline__ void consume1(const float4& n, const float4& typf,
                                         float& sq, float& sq2, float& sqy)
{
    TyPack u; u.f = typf;
    float2 e0 = __half22float2(u.h[0]);
    float2 e1 = __half22float2(u.h[1]);
    float2 e2 = __half22float2(u.h[2]);
    float2 e3 = __half22float2(u.h[3]);
    float qx = ex2f(fmaf(n.x, L2E, e0.x));
    float qy = ex2f(fmaf(n.y, L2E, e1.x));
    float qz = ex2f(fmaf(n.z, L2E, e2.x));
    float qw = ex2f(fmaf(n.w, L2E, e3.x));
    sq  += (qx + qy) + (qz + qw);
    sq2 = fmaf(qx, qx, sq2);   sq2 = fmaf(qy, qy, sq2);
    sq2 = fmaf(qz, qz, sq2);   sq2 = fmaf(qw, qw, sq2);
    sqy = fmaf(qx, e0.y, sqy); sqy = fmaf(qy, e1.y, sqy);
    sqy = fmaf(qz, e2.y, sqy); sqy = fmaf(qw, e3.y, sqy);
}

__global__ __launch_bounds__(THREADS, 1)
void pl_fused(const float* __restrict__ theta,
              const float* __restrict__ y,
              const float* __restrict__ noise,
              float* __restrict__ out)
{
    extern __shared__ char smem_raw[];
    float4* __restrict__ ring = (float4*)smem_raw;                 // [DEPTH][THREADS]
    float4* __restrict__ ty4  = (float4*)(smem_raw + RING_BYTES);  // [D4] of 4x half2
    __shared__ float fin[NWARPS];
    __shared__ float s_sy2;
    __shared__ int   is_last;

    const int b    = blockIdx.x;
    const int tid  = threadIdx.x;
    const int lane = tid & 31;
    const int warp = tid >> 5;

    // ---- stage packed (theta*log2e, y) half2; exact fp32 Sigma(y^2) ----
    float sy2p = 0.0f;
    {
        const float4* __restrict__ th4 = (const float4*)(theta + (size_t)b * D_DIM);
        const float4* __restrict__ yy4 = (const float4*)(y     + (size_t)b * D_DIM);
        for (int i = tid; i < D4; i += THREADS) {
            float4 t = __ldg(th4 + i);
            float4 v = __ldg(yy4 + i);
            sy2p = fmaf(v.x, v.x, sy2p);
            sy2p = fmaf(v.y, v.y, sy2p);
            sy2p = fmaf(v.z, v.z, sy2p);
            sy2p = fmaf(v.w, v.w, sy2p);
            TyPack u;
            u.h[0] = __floats2half2_rn(t.x * L2E, v.x);
            u.h[1] = __floats2half2_rn(t.y * L2E, v.y);
            u.h[2] = __floats2half2_rn(t.z * L2E, v.z);
            u.h[3] = __floats2half2_rn(t.w * L2E, v.w);
            ty4[i] = u.f;
        }
    }
    // block-reduce sy2p -> s_sy2 (prologue only)
    #pragma unroll
    for (int o = 16; o; o >>= 1) sy2p += __shfl_xor_sync(0xffffffffu, sy2p, o);
    if (lane == 0) fin[warp] = sy2p;
    __syncthreads();
    if (tid == 0) {
        float t = fin[0];
        #pragma unroll
        for (int w = 1; w < NWARPS; w++) t += fin[w];
        s_sy2 = t;
    }
    __syncthreads();
    const float sy2 = s_sy2;

    // ---- 2 rounds x 32 warps = 64 samples; cp.async ring; no block barriers ----
    float acc = 0.0f;
    #pragma unroll 1
    for (int r = 0; r < 2; r++) {
        const int s = r * NWARPS + warp;
        const float4* __restrict__ nz =
            (const float4*)(noise + ((size_t)s * B_DIM + b) * D_DIM);

        float sq = 0.0f, sq2 = 0.0f, sqy = 0.0f;

        // prime the ring
        #pragma unroll
        for (int k = 0; k < DEPTH; k++) {
            __pipeline_memcpy_async(&ring[k * THREADS + tid],
                                    nz + k * 32 + lane, 16);
            __pipeline_commit();
        }

        #pragma unroll 2
        for (int j = 0; j < J_FULL; j++) {
            __pipeline_wait_prior(DEPTH - 1);
            float4 n = ring[(j & (DEPTH - 1)) * THREADS + tid];
            const int idx = j * 32 + lane;
            float4 typ = ty4[idx];
            consume1(n, typ, sq, sq2, sqy);
            const int jn = j + DEPTH;
            if (jn < J_FULL)
                __pipeline_memcpy_async(&ring[(j & (DEPTH - 1)) * THREADS + tid],
                                        nz + jn * 32 + lane, 16);
            __pipeline_commit();
        }
        // tail: float4 indices 2496..2499 (lane<4), direct global load
        if (lane < 4) {
            float4 n = __ldcs(nz + 2496 + lane);
            float4 typ = ty4[2496 + lane];
            consume1(n, typ, sq, sq2, sqy);
        }

        // warp-local reductions (the only softmax "sync" needed)
        #pragma unroll
        for (int o = 16; o; o >>= 1) {
            sq  += __shfl_xor_sync(0xffffffffu, sq,  o);
            sq2 += __shfl_xor_sync(0xffffffffu, sq2, o);
            sqy += __shfl_xor_sync(0xffffffffu, sqy, o);
        }
        const float inv = __frcp_rn(sq);
        // loss_s = inv^2*Sq2 - 2*inv*Sqy + Sy2
        acc += fmaf(inv * inv, sq2, fmaf(-2.0f * inv, sqy, sy2));
    }

    // ---- block combine (single barrier) + fused grid reduction ----
    if (lane == 0) fin[warp] = acc;
    __syncthreads();
    if (tid == 0) {
        float tot = fin[0];
        #pragma unroll
        for (int w = 1; w < NWARPS; w++) tot += fin[w];
        g_partial[b] = tot;
        __threadfence();
        unsigned t = atomicAdd(&g_ticket, 1u);
        is_last = (t == B_DIM - 1) ? 1 : 0;
    }
    __syncthreads();

    if (is_last) {
        if (tid < B_DIM) {
            float v = __ldcg(&g_partial[tid]);
            #pragma unroll
            for (int o = 16; o; o >>= 1) v += __shfl_xor_sync(0xffffffffu, v, o);
            if (lane == 0) fin[warp] = v;      // warps 0..3
        }
        __syncthreads();
        if (tid == 0) {
            float tot = fin[0] + fin[1] + fin[2] + fin[3];
            out[0] = tot * (1.0f / ((float)S_DIM * (float)B_DIM * (float)D_DIM));
            g_ticket = 0u;                      // reset for next graph replay
        }
    }
}

extern "C" void kernel_launch(void* const* d_in, const int* in_sizes, int n_in,
                              void* d_out, int out_size)
{
    const float* theta = (const float*)d_in[0];  // [B, D]
    const float* y     = (const float*)d_in[1];  // [B, D]
    const float* noise = (const float*)d_in[2];  // [S, B, D]
    float* out = (float*)d_out;

    cudaFuncSetAttribute(pl_fused,
                         cudaFuncAttributeMaxDynamicSharedMemorySize,
                         SMEM_BYTES);
    pl_fused<<<B_DIM, THREADS, SMEM_BYTES>>>(theta, y, noise, out);
}

// round 8
// speedup vs baseline: 1.1915x; 1.1915x over previous
#include <cuda_runtime.h>

// S=64, B=128, D=10000 fixed by the reference.
#define D_DIM   10000
#define D4      2500
#define J_FULL  78            // 78*32 = 2496 float4; tail = 4 (lane<4)
#define S_DIM   64
#define B_DIM   128
#define THREADS 1024
#define NWARPS  32
#define SMEM_BYTES (2 * D_DIM * sizeof(float))   // 80000 B

#define L2E 1.4426950408889634f

__device__ float    g_partial[B_DIM];
__device__ unsigned g_ticket;      // zero-init; reset by last CTA each launch

__device__ __forceinline__ float ex2f(float x) {
    float r;
    asm("ex2.approx.ftz.f32 %0, %1;" : "=f"(r) : "f"(x));
    return r;
}

// consume one quad (noise n, theta*log2e t, y yv) into one sample's accumulators
__device__ __forceinline__ void consume1(const float4& n, const float4& t,
                                         const float4& yv,
                                         float& sq, float& sq2, float& sqy)
{
    float qx = ex2f(fmaf(n.x, L2E, t.x));
    float qy = ex2f(fmaf(n.y, L2E, t.y));
    float qz = ex2f(fmaf(n.z, L2E, t.z));
    float qw = ex2f(fmaf(n.w, L2E, t.w));
    sq  += (qx + qy) + (qz + qw);
    sq2 = fmaf(qx, qx, sq2);   sq2 = fmaf(qy, qy, sq2);
    sq2 = fmaf(qz, qz, sq2);   sq2 = fmaf(qw, qw, sq2);
    sqy = fmaf(qx, yv.x, sqy); sqy = fmaf(qy, yv.y, sqy);
    sqy = fmaf(qz, yv.z, sqy); sqy = fmaf(qw, yv.w, sqy);
}

__global__ __launch_bounds__(THREADS, 1)
void pl_fused(const float* __restrict__ theta,
              const float* __restrict__ y,
              const float* __restrict__ noise,
              float* __restrict__ out)
{
    extern __shared__ float sm[];          // [0,10000): theta_b*log2e  [10000,20000): y_b
    float* __restrict__ sth = sm;
    float* __restrict__ syy = sm + D_DIM;
    __shared__ float fin[NWARPS];
    __shared__ float s_sy2;
    __shared__ int   is_last;

    const int b    = blockIdx.x;
    const int tid  = threadIdx.x;
    const int lane = tid & 31;
    const int warp = tid >> 5;

    // ---- stage theta_b*log2e, y_b into shared; exact fp32 Sigma(y^2) ----
    float sy2p = 0.0f;
    {
        const float4* __restrict__ th4 = (const float4*)(theta + (size_t)b * D_DIM);
        const float4* __restrict__ yy4 = (const float4*)(y     + (size_t)b * D_DIM);
        float4* s_t = (float4*)sth;
        float4* s_y = (float4*)syy;
        for (int i = tid; i < D4; i += THREADS) {
            float4 t = __ldg(th4 + i);
            float4 v = __ldg(yy4 + i);
            sy2p = fmaf(v.x, v.x, sy2p);
            sy2p = fmaf(v.y, v.y, sy2p);
            sy2p = fmaf(v.z, v.z, sy2p);
            sy2p = fmaf(v.w, v.w, sy2p);
            t.x *= L2E; t.y *= L2E; t.z *= L2E; t.w *= L2E;
            s_t[i] = t;
            s_y[i] = v;
        }
    }
    #pragma unroll
    for (int o = 16; o; o >>= 1) sy2p += __shfl_xor_sync(0xffffffffu, sy2p, o);
    if (lane == 0) fin[warp] = sy2p;
    __syncthreads();
    if (tid == 0) {
        float t = fin[0];
        #pragma unroll
        for (int w = 1; w < NWARPS; w++) t += fin[w];
        s_sy2 = t;
    }
    __syncthreads();
    const float sy2 = s_sy2;

    const float4* __restrict__ st4 = (const float4*)sth;
    const float4* __restrict__ sy4 = (const float4*)syy;

    // ---- each warp interleaves samples sA=warp and sB=warp+32 ----
    const float4* __restrict__ nzA =
        (const float4*)(noise + ((size_t)warp            * B_DIM + b) * D_DIM);
    const float4* __restrict__ nzB =
        (const float4*)(noise + ((size_t)(warp + NWARPS) * B_DIM + b) * D_DIM);

    float aq = 0.0f, aq2 = 0.0f, aqy = 0.0f;   // sample A accumulators
    float bq = 0.0f, bq2 = 0.0f, bqy = 0.0f;   // sample B accumulators

    // rotating 3-deep pipeline per sample
    float4 A0 = __ldcs(nzA + 0 * 32 + lane);
    float4 B0 = __ldcs(nzB + 0 * 32 + lane);
    float4 A1 = __ldcs(nzA + 1 * 32 + lane);
    float4 B1 = __ldcs(nzB + 1 * 32 + lane);
    float4 A2 = __ldcs(nzA + 2 * 32 + lane);
    float4 B2 = __ldcs(nzB + 2 * 32 + lane);

    // 25 blocks: consume j=jj..jj+2, prefetch jj+3..jj+5 (last prefetch = 75,76,77)
    #pragma unroll 1
    for (int jj = 0; jj <= 72; jj += 3) {
        {
            const int idx = jj * 32 + lane;
            float4 t = st4[idx], yv = sy4[idx];
            consume1(A0, t, yv, aq, aq2, aqy);
            consume1(B0, t, yv, bq, bq2, bqy);
            A0 = __ldcs(nzA + idx + 3 * 32);
            B0 = __ldcs(nzB + idx + 3 * 32);
        }
        {
            const int idx = (jj + 1) * 32 + lane;
            float4 t = st4[idx], yv = sy4[idx];
            consume1(A1, t, yv, aq, aq2, aqy);
            consume1(B1, t, yv, bq, bq2, bqy);
            A1 = __ldcs(nzA + idx + 3 * 32);
            B1 = __ldcs(nzB + idx + 3 * 32);
        }
        {
            const int idx = (jj + 2) * 32 + lane;
            float4 t = st4[idx], yv = sy4[idx];
            consume1(A2, t, yv, aq, aq2, aqy);
            consume1(B2, t, yv, bq, bq2, bqy);
            A2 = __ldcs(nzA + idx + 3 * 32);
            B2 = __ldcs(nzB + idx + 3 * 32);
        }
    }

    // tail loads (lane<4): quad index 2496..2499
    float4 tlA, tlB;
    if (lane < 4) {
        tlA = __ldcs(nzA + 2496 + lane);
        tlB = __ldcs(nzB + 2496 + lane);
    }

    // epilogue: consume j=75,76,77 (already loaded into A0..A2/B0..B2)
    {
        const int idx = 75 * 32 + lane;
        float4 t = st4[idx], yv = sy4[idx];
        consume1(A0, t, yv, aq, aq2, aqy);
        consume1(B0, t, yv, bq, bq2, bqy);
    }
    {
        const int idx = 76 * 32 + lane;
        float4 t = st4[idx], yv = sy4[idx];
        consume1(A1, t, yv, aq, aq2, aqy);
        consume1(B1, t, yv, bq, bq2, bqy);
    }
    {
        const int idx = 77 * 32 + lane;
        float4 t = st4[idx], yv = sy4[idx];
        consume1(A2, t, yv, aq, aq2, aqy);
        consume1(B2, t, yv, bq, bq2, bqy);
    }
    if (lane < 4) {
        const int idx = 2496 + lane;
        float4 t = st4[idx], yv = sy4[idx];
        consume1(tlA, t, yv, aq, aq2, aqy);
        consume1(tlB, t, yv, bq, bq2, bqy);
    }

    // warp-local reductions for both samples
    #pragma unroll
    for (int o = 16; o; o >>= 1) {
        aq  += __shfl_xor_sync(0xffffffffu, aq,  o);
        aq2 += __shfl_xor_sync(0xffffffffu, aq2, o);
        aqy += __shfl_xor_sync(0xffffffffu, aqy, o);
        bq  += __shfl_xor_sync(0xffffffffu, bq,  o);
        bq2 += __shfl_xor_sync(0xffffffffu, bq2, o);
        bqy += __shfl_xor_sync(0xffffffffu, bqy, o);
    }
    const float invA = __frcp_rn(aq);
    const float invB = __frcp_rn(bq);
    float acc = fmaf(invA * invA, aq2, fmaf(-2.0f * invA, aqy, sy2))
              + fmaf(invB * invB, bq2, fmaf(-2.0f * invB, bqy, sy2));

    // ---- block combine (single barrier) + fused grid reduction ----
    if (lane == 0) fin[warp] = acc;
    __syncthreads();
    if (tid == 0) {
        float tot = fin[0];
        #pragma unroll
        for (int w = 1; w < NWARPS; w++) tot += fin[w];
        g_partial[b] = tot;
        __threadfence();
        unsigned t = atomicAdd(&g_ticket, 1u);
        is_last = (t == B_DIM - 1) ? 1 : 0;
    }
    __syncthreads();

    if (is_last) {
        if (tid < B_DIM) {
            float v = __ldcg(&g_partial[tid]);
            #pragma unroll
            for (int o = 16; o; o >>= 1) v += __shfl_xor_sync(0xffffffffu, v, o);
            if (lane == 0) fin[warp] = v;      // warps 0..3
        }
        __syncthreads();
        if (tid == 0) {
            float tot = fin[0] + fin[1] + fin[2] + fin[3];
            out[0] = tot * (1.0f / ((float)S_DIM * (float)B_DIM * (float)D_DIM));
            g_ticket = 0u;                      // reset for next graph replay
        }
    }
}

extern "C" void kernel_launch(void* const* d_in, const int* in_sizes, int n_in,
                              void* d_out, int out_size)
{
    const float* theta = (const float*)d_in[0];  // [B, D]
    const float* y     = (const float*)d_in[1];  // [B, D]
    const float* noise = (const float*)d_in[2];  // [S, B, D]
    float* out = (float*)d_out;

    cudaFuncSetAttribute(pl_fused,
                         cudaFuncAttributeMaxDynamicSharedMemorySize,
                         SMEM_BYTES);
    pl_fused<<<B_DIM, THREADS, SMEM_BYTES>>>(theta, y, noise, out);
}